// round 1
// baseline (speedup 1.0000x reference)
#include <cuda_runtime.h>
#include <cuda_bf16.h>
#include <math.h>

#define BATCH 8
#define CH 32
#define HH 256
#define WW 256
#define PLANE (HH*WW)

// Scratch buffers (device globals: allocation-guard safe)
__device__ float g_bufA[BATCH*CH*PLANE];      // 67 MB: conv outputs (32 ch)
__device__ float g_bufB[BATCH*4*CH*PLANE];    // 268 MB: irnn outputs (128 ch)

// ---------------------------------------------------------------------------
// Direct 3x3 conv, pad=1, Cout=32, templated Cin.
// Block = 256 threads computes a 32(W) x 8(H) output tile.
// Thread: cg = cout-group of 8, strip of 4 consecutive W pixels.
// ---------------------------------------------------------------------------
template<int CIN>
__global__ void __launch_bounds__(256) conv3x3_kernel(
    const float* __restrict__ in, const float* __restrict__ wgt,
    float* __restrict__ out, int do_relu)
{
    __shared__ float s_in[10*34];
    __shared__ float s_w[32*9];

    const int b   = blockIdx.z;
    const int oh0 = blockIdx.y * 8;
    const int ow0 = blockIdx.x * 32;
    const int tid = threadIdx.x;
    const int cg  = tid >> 6;          // 0..3 -> couts [cg*8, cg*8+8)
    const int p   = tid & 63;
    const int r   = p >> 3;            // row in tile 0..7
    const int cb  = (p & 7) << 2;      // col base 0,4,...,28

    float4 acc[8];
    #pragma unroll
    for (int i = 0; i < 8; ++i) acc[i] = make_float4(0.f,0.f,0.f,0.f);

    for (int cin = 0; cin < CIN; ++cin) {
        const float* inp = in + ((size_t)(b*CIN + cin))*PLANE;
        // load 10x34 input tile (with zero padding)
        for (int idx = tid; idx < 340; idx += 256) {
            int tr = idx / 34, tc = idx % 34;
            int gh = oh0 - 1 + tr, gw = ow0 - 1 + tc;
            float v = 0.f;
            if (gh >= 0 && gh < HH && gw >= 0 && gw < WW) v = inp[gh*WW + gw];
            s_in[idx] = v;
        }
        // load weights for this cin: [32 couts][9]
        for (int idx = tid; idx < 288; idx += 256) {
            int co = idx / 9, k = idx % 9;
            s_w[idx] = wgt[((size_t)(co*CIN + cin))*9 + k];
        }
        __syncthreads();

        // read 3x6 input patch
        float xv[3][6];
        #pragma unroll
        for (int dr = 0; dr < 3; ++dr)
            #pragma unroll
            for (int dc = 0; dc < 6; ++dc)
                xv[dr][dc] = s_in[(r+dr)*34 + cb + dc];

        #pragma unroll
        for (int co = 0; co < 8; ++co) {
            const float* wp = &s_w[(cg*8 + co)*9];
            #pragma unroll
            for (int kh = 0; kh < 3; ++kh) {
                #pragma unroll
                for (int kw = 0; kw < 3; ++kw) {
                    float wv = wp[kh*3 + kw];
                    acc[co].x = fmaf(wv, xv[kh][0+kw], acc[co].x);
                    acc[co].y = fmaf(wv, xv[kh][1+kw], acc[co].y);
                    acc[co].z = fmaf(wv, xv[kh][2+kw], acc[co].z);
                    acc[co].w = fmaf(wv, xv[kh][3+kw], acc[co].w);
                }
            }
        }
        __syncthreads();
    }

    const int oh = oh0 + r, ow = ow0 + cb;
    #pragma unroll
    for (int co = 0; co < 8; ++co) {
        float4 v = acc[co];
        if (do_relu) {
            v.x = fmaxf(v.x, 0.f); v.y = fmaxf(v.y, 0.f);
            v.z = fmaxf(v.z, 0.f); v.w = fmaxf(v.w, 0.f);
        }
        int cout = cg*8 + co;
        *(float4*)&out[(((size_t)b*32 + cout)*HH + oh)*WW + ow] = v;
    }
}

// ---------------------------------------------------------------------------
// Vertical scans (up + down), one thread per (b,c,w) column. Coalesced.
// Output channel layout: up -> base 0, down -> base 64 (of 128).
// h[0] = x[0] (passthrough), h[i] = relu(x[i] + w*h[i-1] + b)
// ---------------------------------------------------------------------------
__global__ void scan_v_kernel(const float* __restrict__ in, float* __restrict__ out,
                              const float* __restrict__ wv, const float* __restrict__ bv)
{
    int tid = blockIdx.x*blockDim.x + threadIdx.x;   // B*C*W threads
    int w = tid & (WW-1);
    int c = (tid >> 8) & 31;
    int b = tid >> 13;

    const float wu = wv[0*32 + c], bu = bv[0*32 + c];   // up
    const float wd = wv[2*32 + c], bd = bv[2*32 + c];   // down

    const float* xp   = in  + ((size_t)(b*32 + c))*PLANE + w;
    float* outU = out + ((size_t)(b*128 +  0 + c))*PLANE + w;
    float* outD = out + ((size_t)(b*128 + 64 + c))*PLANE + w;

    // down: forward along h
    float s = xp[0];
    outD[0] = s;
    #pragma unroll 4
    for (int h = 1; h < HH; ++h) {
        s = fmaxf(fmaf(wd, s, xp[h*WW] + bd), 0.f);
        outD[h*WW] = s;
    }
    // up: backward along h
    s = xp[(HH-1)*WW];
    outU[(HH-1)*WW] = s;
    #pragma unroll 4
    for (int h = HH-2; h >= 0; --h) {
        s = fmaxf(fmaf(wu, s, xp[h*WW] + bu), 0.f);
        outU[h*WW] = s;
    }
}

// ---------------------------------------------------------------------------
// Horizontal scans (right + left), one thread per (b,c,h) row.
// right -> base 32, left -> base 96.
// ---------------------------------------------------------------------------
__global__ void scan_h_kernel(const float* __restrict__ in, float* __restrict__ out,
                              const float* __restrict__ wv, const float* __restrict__ bv)
{
    int tid = blockIdx.x*blockDim.x + threadIdx.x;   // B*C*H threads
    int h = tid & (HH-1);
    int c = (tid >> 8) & 31;
    int b = tid >> 13;

    const float wr = wv[1*32 + c], br = bv[1*32 + c];   // right
    const float wl = wv[3*32 + c], bl = bv[3*32 + c];   // left

    const float* xp   = in  + (((size_t)(b*32 + c))*HH + h)*WW;
    float* outR = out + (((size_t)(b*128 + 32 + c))*HH + h)*WW;
    float* outL = out + (((size_t)(b*128 + 96 + c))*HH + h)*WW;

    float s = xp[0];
    outR[0] = s;
    #pragma unroll 4
    for (int w = 1; w < WW; ++w) {
        s = fmaxf(fmaf(wr, s, xp[w] + br), 0.f);
        outR[w] = s;
    }
    s = xp[WW-1];
    outL[WW-1] = s;
    #pragma unroll 4
    for (int w = WW-2; w >= 0; --w) {
        s = fmaxf(fmaf(wl, s, xp[w] + bl), 0.f);
        outL[w] = s;
    }
}

// ---------------------------------------------------------------------------
// 1x1 conv (32 -> 1) + sigmoid. Input already has relu applied (fused in conv3).
// ---------------------------------------------------------------------------
__global__ void convout_kernel(const float* __restrict__ in, const float* __restrict__ w,
                               float* __restrict__ out)
{
    int idx = blockIdx.x*blockDim.x + threadIdx.x;   // B*H*W
    if (idx >= BATCH*PLANE) return;
    int b  = idx >> 16;
    int hw = idx & 65535;
    const float* p = in + ((size_t)b*32)*PLANE + hw;
    float s = 0.f;
    #pragma unroll
    for (int c = 0; c < 32; ++c) s = fmaf(w[c], p[(size_t)c*PLANE], s);
    out[idx] = 1.f/(1.f + expf(-s));
}

// ---------------------------------------------------------------------------
extern "C" void kernel_launch(void* const* d_in, const int* in_sizes, int n_in,
                              void* d_out, int out_size)
{
    const float* x          = (const float*)d_in[0];
    const float* conv_in_w  = (const float*)d_in[1];
    const float* conv2_w    = (const float*)d_in[2];
    const float* conv3_w    = (const float*)d_in[3];
    const float* conv_out_w = (const float*)d_in[4];
    const float* irnn1_w    = (const float*)d_in[5];
    const float* irnn1_b    = (const float*)d_in[6];
    const float* irnn2_w    = (const float*)d_in[7];
    const float* irnn2_b    = (const float*)d_in[8];
    float* out = (float*)d_out;

    float* A; cudaGetSymbolAddress((void**)&A, g_bufA);
    float* Bb; cudaGetSymbolAddress((void**)&Bb, g_bufB);

    dim3 cgrid(WW/32, HH/8, BATCH);   // (8, 32, 8)

    // stage 1: conv_in (32->32)
    conv3x3_kernel<32><<<cgrid, 256>>>(x, conv_in_w, A, 0);
    // irnn1
    scan_v_kernel<<<BATCH*CH*WW/256, 256>>>(A, Bb, irnn1_w, irnn1_b);
    scan_h_kernel<<<BATCH*CH*HH/256, 256>>>(A, Bb, irnn1_w, irnn1_b);
    // conv2 (128->32)
    conv3x3_kernel<128><<<cgrid, 256>>>(Bb, conv2_w, A, 0);
    // irnn2
    scan_v_kernel<<<BATCH*CH*WW/256, 256>>>(A, Bb, irnn2_w, irnn2_b);
    scan_h_kernel<<<BATCH*CH*HH/256, 256>>>(A, Bb, irnn2_w, irnn2_b);
    // conv3 (128->32) + relu
    conv3x3_kernel<128><<<cgrid, 256>>>(Bb, conv3_w, A, 1);
    // 1x1 conv + sigmoid
    convout_kernel<<<BATCH*PLANE/256, 256>>>(A, conv_out_w, out);
}

// round 2
// speedup vs baseline: 1.4269x; 1.4269x over previous
#include <cuda_runtime.h>
#include <math.h>

#define BATCH 8
#define CH 32
#define HH 256
#define WW 256
#define PLANE (HH*WW)

typedef unsigned long long ull;

// Scratch (device globals: allocation-guard safe)
__device__ float g_bufA[BATCH*CH*PLANE];            // 67 MB conv outputs
__device__ float g_bufB[BATCH*4*CH*PLANE];          // 268 MB irnn outputs
__device__ __align__(16) float g_wT[128*32*9*2];    // transposed+duplicated weights

// ---------------------------------------------------------------------------
// f32x2 packed math helpers (sm_100 PTX)
// ---------------------------------------------------------------------------
__device__ __forceinline__ ull pack2(float lo, float hi) {
    ull d;
    asm("mov.b64 %0, {%1, %2};" : "=l"(d)
        : "r"(__float_as_uint(lo)), "r"(__float_as_uint(hi)));
    return d;
}
__device__ __forceinline__ void unpack2(ull v, float& lo, float& hi) {
    unsigned a, b;
    asm("mov.b64 {%0, %1}, %2;" : "=r"(a), "=r"(b) : "l"(v));
    lo = __uint_as_float(a); hi = __uint_as_float(b);
}
__device__ __forceinline__ ull fma2(ull a, ull b, ull c) {
    ull d;
    asm("fma.rn.f32x2 %0, %1, %2, %3;" : "=l"(d) : "l"(a), "l"(b), "l"(c));
    return d;
}

// ---------------------------------------------------------------------------
// cp.async helpers
// ---------------------------------------------------------------------------
__device__ __forceinline__ unsigned smem_u32(const void* p) {
    return (unsigned)__cvta_generic_to_shared(p);
}
__device__ __forceinline__ void cp_async4(unsigned dst, const void* src, bool pred) {
    asm volatile("cp.async.ca.shared.global [%0], [%1], 4, %2;"
                 :: "r"(dst), "l"(src), "r"(pred ? 4u : 0u));
}
__device__ __forceinline__ void cp_async16(unsigned dst, const void* src) {
    asm volatile("cp.async.cg.shared.global [%0], [%1], 16;" :: "r"(dst), "l"(src));
}
__device__ __forceinline__ void cp_commit() { asm volatile("cp.async.commit_group;"); }
template<int N> __device__ __forceinline__ void cp_wait() {
    asm volatile("cp.async.wait_group %0;" :: "n"(N));
}

// ---------------------------------------------------------------------------
// Weight transpose+duplicate: w[cout][cin][9] -> wd[cin][cout][9] as f32x2(v,v)
// ---------------------------------------------------------------------------
__global__ void wtrans_kernel(const float* __restrict__ w, float* __restrict__ wd, int cin)
{
    int i = blockIdx.x*blockDim.x + threadIdx.x;
    if (i >= 32*cin*9) return;
    int k  = i % 9;
    int ci = (i/9) % cin;
    int co = i/(9*cin);
    float v = w[i];
    int o = ((ci*32 + co)*9 + k)*2;
    wd[o] = v; wd[o+1] = v;
}

// ---------------------------------------------------------------------------
// Direct 3x3 conv, pad=1, Cout=32, f32x2 FMAs, cp.async double buffering.
// Block 256 threads -> 32(W) x 8(H) output tile; thread: 8 couts x 4 pixels.
// EPI=0: plain store of 32 channels. EPI=1: fused relu + 1x1 conv + sigmoid.
// ---------------------------------------------------------------------------
template<int CIN, int EPI>
__global__ void __launch_bounds__(256, 3) conv3x3_kernel(
    const float* __restrict__ in, const float* __restrict__ wdup,
    float* __restrict__ out, const float* __restrict__ mask_w)
{
    constexpr int NST = CIN/4;                       // 4 cin per stage
    __shared__ float s_in[2][4*350];                 // per cin: 10 rows, stride 35
    __shared__ __align__(16) float2 s_w[2][4*288];   // per cin: 32 couts * 9 taps dup'd
    __shared__ float s_red[256][4];                  // EPI=1 reduction

    const int b   = blockIdx.z;
    const int oh0 = blockIdx.y * 8;
    const int ow0 = blockIdx.x * 32;
    const int tid = threadIdx.x;
    const int cg  = tid >> 6;           // cout group (8 couts)
    const int p   = tid & 63;
    const int r   = p >> 3;             // tile row 0..7
    const int cb  = (p & 7) << 2;       // col base 0,4,...,28

    ull acc[8][2];
    #pragma unroll
    for (int co = 0; co < 8; ++co) { acc[co][0] = 0ull; acc[co][1] = 0ull; }

    auto load_stage = [&](int c0, int buf) {
        const float* base = in + ((size_t)b*CIN + c0)*PLANE;
        for (int i = tid; i < 4*340; i += 256) {
            int ci  = i / 340;
            int rem = i - ci*340;
            int tr  = rem / 34;
            int tc  = rem - tr*34;
            int gh  = oh0 - 1 + tr;
            int gw  = ow0 - 1 + tc;
            bool ok = ((unsigned)gh < HH) && ((unsigned)gw < WW);
            const float* src = base + (size_t)ci*PLANE + (ok ? gh*WW + gw : 0);
            cp_async4(smem_u32(&s_in[buf][ci*350 + tr*35 + tc]), src, ok);
        }
        const float4* wsrc = (const float4*)(wdup + (size_t)c0*576);
        float4* wdst = (float4*)&s_w[buf][0];
        for (int i = tid; i < 576; i += 256)
            cp_async16(smem_u32(&wdst[i]), &wsrc[i]);
        cp_commit();
    };

    load_stage(0, 0);

    for (int st = 0; st < NST; ++st) {
        if (st + 1 < NST) { load_stage((st+1)*4, (st+1)&1); cp_wait<1>(); }
        else              { cp_wait<0>(); }
        __syncthreads();

        const float*  si  = &s_in[st&1][0];
        const float2* swb = &s_w[st&1][0];

        #pragma unroll
        for (int ci = 0; ci < 4; ++ci) {
            const float*  sp = si + ci*350 + r*35 + cb;
            const float2* wp = swb + ci*288 + cg*72;
            #pragma unroll
            for (int kh = 0; kh < 3; ++kh) {
                const float* rowp = sp + kh*35;
                float x0 = rowp[0], x1 = rowp[1], x2 = rowp[2];
                float x3 = rowp[3], x4 = rowp[4], x5 = rowp[5];
                ull P0 = pack2(x0, x1);
                ull P1 = pack2(x1, x2);
                ull P2 = pack2(x2, x3);
                ull P3 = pack2(x3, x4);
                ull P4 = pack2(x4, x5);
                #pragma unroll
                for (int co = 0; co < 8; ++co) {
                    const float2* wq = wp + co*9 + kh*3;
                    ull w0 = *(const ull*)&wq[0];
                    ull w1 = *(const ull*)&wq[1];
                    ull w2 = *(const ull*)&wq[2];
                    acc[co][0] = fma2(w0, P0, acc[co][0]);
                    acc[co][1] = fma2(w0, P2, acc[co][1]);
                    acc[co][0] = fma2(w1, P1, acc[co][0]);
                    acc[co][1] = fma2(w1, P3, acc[co][1]);
                    acc[co][0] = fma2(w2, P2, acc[co][0]);
                    acc[co][1] = fma2(w2, P4, acc[co][1]);
                }
            }
        }
        __syncthreads();
    }

    if (EPI == 0) {
        const int oh = oh0 + r, ow = ow0 + cb;
        #pragma unroll
        for (int co = 0; co < 8; ++co) {
            float4 v;
            unpack2(acc[co][0], v.x, v.y);
            unpack2(acc[co][1], v.z, v.w);
            int cout = cg*8 + co;
            *(float4*)&out[(((size_t)b*32 + cout)*HH + oh)*WW + ow] = v;
        }
    } else {
        // fused: relu -> 1x1 conv (32->1) partial per cg -> smem reduce -> sigmoid
        float part[4] = {0.f, 0.f, 0.f, 0.f};
        #pragma unroll
        for (int co = 0; co < 8; ++co) {
            float v0, v1, v2, v3;
            unpack2(acc[co][0], v0, v1);
            unpack2(acc[co][1], v2, v3);
            float wv = __ldg(&mask_w[cg*8 + co]);
            part[0] = fmaf(wv, fmaxf(v0, 0.f), part[0]);
            part[1] = fmaf(wv, fmaxf(v1, 0.f), part[1]);
            part[2] = fmaf(wv, fmaxf(v2, 0.f), part[2]);
            part[3] = fmaf(wv, fmaxf(v3, 0.f), part[3]);
        }
        #pragma unroll
        for (int j = 0; j < 4; ++j)
            s_red[r*32 + cb + j][cg] = part[j];
        __syncthreads();
        // 256 threads, one pixel each
        float sum = s_red[tid][0] + s_red[tid][1] + s_red[tid][2] + s_red[tid][3];
        float sig = 1.f / (1.f + expf(-sum));
        int rr = tid >> 5, cc = tid & 31;
        out[((size_t)b*HH + oh0 + rr)*WW + ow0 + cc] = sig;
    }
}

// ---------------------------------------------------------------------------
// Vertical scans (up+down): 1 thread per (b,c,w) column, coalesced.
// up -> ch base 0, down -> ch base 64.
// ---------------------------------------------------------------------------
__global__ void scan_v_kernel(const float* __restrict__ in, float* __restrict__ out,
                              const float* __restrict__ wv, const float* __restrict__ bv)
{
    int tid = blockIdx.x*blockDim.x + threadIdx.x;   // B*C*W
    int w = tid & (WW-1);
    int c = (tid >> 8) & 31;
    int b = tid >> 13;

    const float wu = wv[0*32 + c], bu = bv[0*32 + c];
    const float wd = wv[2*32 + c], bd = bv[2*32 + c];

    const float* xp = in  + ((size_t)(b*32 + c))*PLANE + w;
    float* outU = out + ((size_t)(b*128 +  0 + c))*PLANE + w;
    float* outD = out + ((size_t)(b*128 + 64 + c))*PLANE + w;

    float s = xp[0];
    outD[0] = s;
    #pragma unroll 4
    for (int h = 1; h < HH; ++h) {
        s = fmaxf(fmaf(wd, s, xp[h*WW] + bd), 0.f);
        outD[h*WW] = s;
    }
    s = xp[(HH-1)*WW];
    outU[(HH-1)*WW] = s;
    #pragma unroll 4
    for (int h = HH-2; h >= 0; --h) {
        s = fmaxf(fmaf(wu, s, xp[h*WW] + bu), 0.f);
        outU[h*WW] = s;
    }
}

// ---------------------------------------------------------------------------
// Horizontal scans (right+left), coalesced via smem tiles.
// Block = 128 threads handles 128 rows of one (b,c); chunks of 32 cols.
// right -> ch base 32, left -> ch base 96.
// ---------------------------------------------------------------------------
__global__ void __launch_bounds__(128) scan_h_kernel(
    const float* __restrict__ in, float* __restrict__ out,
    const float* __restrict__ wv, const float* __restrict__ bv)
{
    __shared__ float sm[128][33];
    const int half = blockIdx.x;     // 0/1 -> rows [half*128, half*128+128)
    const int c    = blockIdx.y;
    const int b    = blockIdx.z;
    const int tid  = threadIdx.x;

    const float wr = wv[1*32 + c], br = bv[1*32 + c];
    const float wl = wv[3*32 + c], bl = bv[3*32 + c];

    const float* xp = in  + ((size_t)(b*32 + c))*PLANE + (size_t)half*128*WW;
    float* outR = out + ((size_t)(b*128 + 32 + c))*PLANE + (size_t)half*128*WW;
    float* outL = out + ((size_t)(b*128 + 96 + c))*PLANE + (size_t)half*128*WW;

    float s = 0.f;
    // forward pass -> right
    for (int ch = 0; ch < 8; ++ch) {
        const int w0 = ch*32;
        #pragma unroll
        for (int k = 0; k < 8; ++k) {
            int f4 = k*128 + tid;
            int row = f4 >> 3, col4 = (f4 & 7) << 2;
            float4 v = *(const float4*)&xp[row*WW + w0 + col4];
            sm[row][col4] = v.x; sm[row][col4+1] = v.y;
            sm[row][col4+2] = v.z; sm[row][col4+3] = v.w;
        }
        __syncthreads();
        #pragma unroll
        for (int w = 0; w < 32; ++w) {
            float x = sm[tid][w];
            s = (ch == 0 && w == 0) ? x : fmaxf(fmaf(wr, s, x + br), 0.f);
            sm[tid][w] = s;
        }
        __syncthreads();
        #pragma unroll
        for (int k = 0; k < 8; ++k) {
            int f4 = k*128 + tid;
            int row = f4 >> 3, col4 = (f4 & 7) << 2;
            float4 v = make_float4(sm[row][col4], sm[row][col4+1],
                                   sm[row][col4+2], sm[row][col4+3]);
            *(float4*)&outR[row*WW + w0 + col4] = v;
        }
        __syncthreads();
    }
    // backward pass -> left
    s = 0.f;
    for (int ch = 7; ch >= 0; --ch) {
        const int w0 = ch*32;
        #pragma unroll
        for (int k = 0; k < 8; ++k) {
            int f4 = k*128 + tid;
            int row = f4 >> 3, col4 = (f4 & 7) << 2;
            float4 v = *(const float4*)&xp[row*WW + w0 + col4];
            sm[row][col4] = v.x; sm[row][col4+1] = v.y;
            sm[row][col4+2] = v.z; sm[row][col4+3] = v.w;
        }
        __syncthreads();
        #pragma unroll
        for (int w = 31; w >= 0; --w) {
            float x = sm[tid][w];
            s = (ch == 7 && w == 31) ? x : fmaxf(fmaf(wl, s, x + bl), 0.f);
            sm[tid][w] = s;
        }
        __syncthreads();
        #pragma unroll
        for (int k = 0; k < 8; ++k) {
            int f4 = k*128 + tid;
            int row = f4 >> 3, col4 = (f4 & 7) << 2;
            float4 v = make_float4(sm[row][col4], sm[row][col4+1],
                                   sm[row][col4+2], sm[row][col4+3]);
            *(float4*)&outL[row*WW + w0 + col4] = v;
        }
        __syncthreads();
    }
}

// ---------------------------------------------------------------------------
extern "C" void kernel_launch(void* const* d_in, const int* in_sizes, int n_in,
                              void* d_out, int out_size)
{
    const float* x          = (const float*)d_in[0];
    const float* conv_in_w  = (const float*)d_in[1];
    const float* conv2_w    = (const float*)d_in[2];
    const float* conv3_w    = (const float*)d_in[3];
    const float* conv_out_w = (const float*)d_in[4];
    const float* irnn1_w    = (const float*)d_in[5];
    const float* irnn1_b    = (const float*)d_in[6];
    const float* irnn2_w    = (const float*)d_in[7];
    const float* irnn2_b    = (const float*)d_in[8];
    float* out = (float*)d_out;

    float* A;  cudaGetSymbolAddress((void**)&A,  g_bufA);
    float* Bb; cudaGetSymbolAddress((void**)&Bb, g_bufB);
    float* Wt; cudaGetSymbolAddress((void**)&Wt, g_wT);

    dim3 cgrid(WW/32, HH/8, BATCH);   // (8, 32, 8)
    dim3 hgrid(2, 32, BATCH);

    // conv_in (32->32)
    wtrans_kernel<<<(32*32*9 + 255)/256, 256>>>(conv_in_w, Wt, 32);
    conv3x3_kernel<32, 0><<<cgrid, 256>>>(x, Wt, A, nullptr);
    // irnn1
    scan_v_kernel<<<BATCH*CH*WW/256, 256>>>(A, Bb, irnn1_w, irnn1_b);
    scan_h_kernel<<<hgrid, 128>>>(A, Bb, irnn1_w, irnn1_b);
    // conv2 (128->32)
    wtrans_kernel<<<(32*128*9 + 255)/256, 256>>>(conv2_w, Wt, 128);
    conv3x3_kernel<128, 0><<<cgrid, 256>>>(Bb, Wt, A, nullptr);
    // irnn2
    scan_v_kernel<<<BATCH*CH*WW/256, 256>>>(A, Bb, irnn2_w, irnn2_b);
    scan_h_kernel<<<hgrid, 128>>>(A, Bb, irnn2_w, irnn2_b);
    // conv3 (128->32) + relu + 1x1 + sigmoid, fused
    wtrans_kernel<<<(32*128*9 + 255)/256, 256>>>(conv3_w, Wt, 128);
    conv3x3_kernel<128, 1><<<cgrid, 256>>>(Bb, Wt, out, conv_out_w);
}